// round 4
// baseline (speedup 1.0000x reference)
#include <cuda_runtime.h>
#include <math.h>

// Problem constants
#define BSZ   1024
#define KDIM  256
#define NPTS  128
#define LOG2PI_F 1.8378770664093453f
#define LOG1P_HALF 0.40546510810816438f

// Output layout offsets
#define OFF_SAMPLED 0
#define OFF_GEN     524288
#define OFF_REAL    655360
#define OFF_LOSSA   786432
#define OFF_LOSSB   917504

// GEMM tiling: 32x32 tile, 128 threads, micro 2(m) x 4(n), full-K smem
#define BM 32
#define BN 32
#define AS_LD 260          // 256 + 4 pad (keeps 16B align, breaks bank alignment)
#define WS_LD 258          // 256 + 2 pad (8B align for LDS.64, bank shift 2)
#define SMEM_WORDS (BM * AS_LD + BN * WS_LD)
#define SMEM_BYTES (SMEM_WORDS * 4)

typedef unsigned long long ull;

// Scratch (device globals: no allocation allowed)
__device__ float g_bufA[BSZ * KDIM];
__device__ float g_bufB[BSZ * KDIM];
__device__ float g_mu[BSZ * KDIM];     // (B, N, 2) flattened
__device__ float g_WpT[KDIM * 256];    // Wp transposed to [H][n*2+k]

__device__ __forceinline__ void ffma2(ull& d, ull a, ull b) {
    asm("fma.rn.f32x2 %0, %1, %2, %0;" : "+l"(d) : "l"(a), "l"(b));
}
__device__ __forceinline__ float pair_sum(ull v) {
    union { ull u; float f[2]; } c; c.u = v;
    return c.f[0] + c.f[1];
}

// ---------------------------------------------------------------------------
// Transpose Wp (N,H,2) -> WpT[h][n*2+k]
// ---------------------------------------------------------------------------
__global__ __launch_bounds__(256) void transpose_wp_kernel(const float* __restrict__ Wp,
                                                           float* __restrict__ WpT) {
    int idx = blockIdx.x * 256 + threadIdx.x;   // 0..65535
    int h = idx >> 8;
    int col = idx & 255;                        // col = n*2 + k
    WpT[idx] = Wp[(col >> 1) * 512 + h * 2 + (col & 1)];
}

// ---------------------------------------------------------------------------
// fp32 GEMM with packed f32x2 FMA: C[1024,256] = act(A @ W + bias + addc)
// A row-major in smem; W transposed to [n][k] in smem; reduction paired on k.
// Grid (256/32, 1024/32) = (8, 32) = 256 CTAs, 128 threads.
// ---------------------------------------------------------------------------
__global__ __launch_bounds__(128) void gemm_kernel(
    const float* __restrict__ A, const float* __restrict__ W,
    const float* __restrict__ bias, float* __restrict__ C,
    int doRelu, float addc)
{
    extern __shared__ float smem[];
    float* As  = smem;                 // [BM][AS_LD], row-major in k
    float* Wst = smem + BM * AS_LD;    // [BN][WS_LD], n-major rows, k contiguous

    const int t  = threadIdx.x;
    const int m0 = blockIdx.y * BM;
    const int n0 = blockIdx.x * BN;

    // ---- prologue: coalesced loads ----
    // As: 32 rows x 64 float4 = 2048 float4
#pragma unroll
    for (int it = 0; it < 16; it++) {
        int idx = it * 128 + t;
        int r = idx >> 6, q = idx & 63;
        float4 v = *(const float4*)&A[(m0 + r) * KDIM + q * 4];
        *(float4*)&As[r * AS_LD + q * 4] = v;
    }
    // Wst: transpose W[k][n0+..] -> Wst[n][k]; 256 k x 8 float4 = 2048 float4
#pragma unroll
    for (int it = 0; it < 16; it++) {
        int idx = it * 128 + t;
        int k = idx >> 3, q = idx & 7;
        float4 v = *(const float4*)&W[k * 256 + n0 + q * 4];
        Wst[(q * 4 + 0) * WS_LD + k] = v.x;
        Wst[(q * 4 + 1) * WS_LD + k] = v.y;
        Wst[(q * 4 + 2) * WS_LD + k] = v.z;
        Wst[(q * 4 + 3) * WS_LD + k] = v.w;
    }
    __syncthreads();

    const int tx = t & 7;      // 0..7  -> cols 4*tx .. 4*tx+3
    const int ty = t >> 3;     // 0..15 -> rows 2*ty, 2*ty+1

    const float* aBase = &As[(2 * ty) * AS_LD];
    const float* bBase = &Wst[(4 * tx) * WS_LD];

    ull acc[2][4];
#pragma unroll
    for (int i = 0; i < 2; i++)
#pragma unroll
        for (int j = 0; j < 4; j++) acc[i][j] = 0ull;

#pragma unroll 8
    for (int kp = 0; kp < KDIM / 2; kp++) {
        const int k = 2 * kp;
        ull A0 = *(const ull*)(aBase + k);
        ull A1 = *(const ull*)(aBase + AS_LD + k);
        ull B0 = *(const ull*)(bBase + k);
        ull B1 = *(const ull*)(bBase + WS_LD + k);
        ull B2 = *(const ull*)(bBase + 2 * WS_LD + k);
        ull B3 = *(const ull*)(bBase + 3 * WS_LD + k);
        ffma2(acc[0][0], A0, B0);
        ffma2(acc[0][1], A0, B1);
        ffma2(acc[0][2], A0, B2);
        ffma2(acc[0][3], A0, B3);
        ffma2(acc[1][0], A1, B0);
        ffma2(acc[1][1], A1, B1);
        ffma2(acc[1][2], A1, B2);
        ffma2(acc[1][3], A1, B3);
    }

    // ---- epilogue ----
    float4 bv = *(const float4*)&bias[n0 + tx * 4];
    float bb[4] = {bv.x + addc, bv.y + addc, bv.z + addc, bv.w + addc};
#pragma unroll
    for (int i = 0; i < 2; i++) {
        float4 v;
        v.x = pair_sum(acc[i][0]) + bb[0];
        v.y = pair_sum(acc[i][1]) + bb[1];
        v.z = pair_sum(acc[i][2]) + bb[2];
        v.w = pair_sum(acc[i][3]) + bb[3];
        if (doRelu) {
            v.x = fmaxf(v.x, 0.0f); v.y = fmaxf(v.y, 0.0f);
            v.z = fmaxf(v.z, 0.0f); v.w = fmaxf(v.w, 0.0f);
        }
        *(float4*)&C[(m0 + 2 * ty + i) * 256 + n0 + tx * 4] = v;
    }
}

// ---------------------------------------------------------------------------
// Fused tail: one CTA per batch row b; thread = (n, s), tid = 2n + s.
// ---------------------------------------------------------------------------
__global__ __launch_bounds__(256) void tail_kernel(
    const float* __restrict__ realPoints,
    const float* __restrict__ predMu,
    const float* __restrict__ predScale,
    const float* __restrict__ eps,
    float* __restrict__ out)
{
    const int b = blockIdx.x;
    __shared__ float mu_s[256];      // (n,k)
    __shared__ float am[128];        // -0.5/dev_m^2
    __shared__ float cm[128];        // -2*log(dev_m) - LOG2PI
    __shared__ float sc[7];

    const int tid = threadIdx.x;
    mu_s[tid] = g_mu[b * 256 + tid];
    if (tid < 128) {
        float dev = 0.001f + (float)tid * (0.009f / 127.0f);
        am[tid] = -0.5f / (dev * dev);
        cm[tid] = -2.0f * logf(dev) - LOG2PI_F;
    }
    if (tid == 0) {
        sc[0] = realPoints[b * 2];
        sc[1] = realPoints[b * 2 + 1];
        sc[2] = predMu[b * 2];
        sc[3] = predMu[b * 2 + 1];
        float p0 = predScale[b * 2], p1 = predScale[b * 2 + 1];
        sc[4] = 1.0f / p0;
        sc[5] = 1.0f / p1;
        sc[6] = logf(p0) + logf(p1);
    }
    __syncthreads();

    const int n = tid >> 1;
    const int s = tid & 1;

    const float mu0 = mu_s[2 * n];
    const float mu1 = mu_s[2 * n + 1];
    const float dev = 0.001f + (float)n * (0.009f / 127.0f);

    const int eoff = s * (BSZ * NPTS * 2) + (b * NPTS + n) * 2;
    const float e0 = eps[eoff];
    const float e1 = eps[eoff + 1];
    const float s0 = fmaf(dev, e0, mu0);
    const float s1 = fmaf(dev, e1, mu1);

    {
        long so = ((long)(s * NPTS + n) * BSZ + b) * 2;
        out[OFF_SAMPLED + so]     = s0;
        out[OFF_SAMPLED + so + 1] = s1;
    }

    // lossB: softmax over m, pick diag m=n
    float sumexp = 0.0f;
    float en = 0.0f;
#pragma unroll 4
    for (int m = 0; m < 128; m++) {
        float d0 = s0 - mu_s[2 * m];
        float d1 = s1 - mu_s[2 * m + 1];
        float ss = fmaf(d0, d0, d1 * d1);
        float lb = fmaf(ss, am[m], cm[m]);
        float e  = __expf(lb);
        sumexp += e;
        if (m == n) en = e;
    }
    float diag = en / sumexp;
    float lbv  = 1.0f - diag;
    out[OFF_LOSSB + b * 256 + tid] = lbv * lbv;

    float z0 = (s0 - sc[2]) * sc[4];
    float z1 = (s1 - sc[3]) * sc[5];
    float lp = fmaf(-0.5f, fmaf(z0, z0, z1 * z1), -sc[6] - LOG2PI_F);
    float gl  = 1.0f / (1.0f + __expf(-lp));
    float sgn = 1.0f / (1.0f + __expf(lp));
    float tA  = LOG1P_HALF - log1pf(sgn);
    tA *= tA;

    float gl_o = __shfl_xor_sync(0xffffffffu, gl, 1);
    float tA_o = __shfl_xor_sync(0xffffffffu, tA, 1);

    if (s == 0) {
        float glm   = 0.5f * (gl + gl_o);
        float lossA = 0.5f * (tA + tA_o);
        float dr0 = sc[0] - mu0;
        float dr1 = sc[1] - mu1;
        float ssr = fmaf(dr0, dr0, dr1 * dr1);
        float rlp = fmaf(ssr, am[n], cm[n]);
        float rl  = 1.0f / (1.0f + __expf(-rlp));
        out[OFF_REAL  + b * NPTS + n] = rl;
        out[OFF_LOSSA + b * NPTS + n] = lossA;
        out[OFF_GEN   + b * NPTS + n] = glm * (1.0f - rl);
    }
}

// ---------------------------------------------------------------------------
extern "C" void kernel_launch(void* const* d_in, const int* in_sizes, int n_in,
                              void* d_out, int out_size) {
    const float* latents    = (const float*)d_in[0];
    const float* realPoints = (const float*)d_in[1];
    const float* predMu     = (const float*)d_in[2];
    const float* predScale  = (const float*)d_in[3];
    const float* eps        = (const float*)d_in[4];
    const float* W[5]  = {(const float*)d_in[5],  (const float*)d_in[7],
                          (const float*)d_in[9],  (const float*)d_in[11],
                          (const float*)d_in[13]};
    const float* bb[5] = {(const float*)d_in[6],  (const float*)d_in[8],
                          (const float*)d_in[10], (const float*)d_in[12],
                          (const float*)d_in[14]};
    const float* Wp = (const float*)d_in[15];
    const float* bp = (const float*)d_in[16];
    float* out = (float*)d_out;

    float *bufA, *bufB, *mu, *WpT;
    cudaGetSymbolAddress((void**)&bufA, g_bufA);
    cudaGetSymbolAddress((void**)&bufB, g_bufB);
    cudaGetSymbolAddress((void**)&mu,   g_mu);
    cudaGetSymbolAddress((void**)&WpT,  g_WpT);

    cudaFuncSetAttribute(gemm_kernel,
                         cudaFuncAttributeMaxDynamicSharedMemorySize, SMEM_BYTES);

    transpose_wp_kernel<<<256, 256>>>(Wp, WpT);

    dim3 ggrid(KDIM / BN, BSZ / BM);   // (8, 32) = 256 CTAs
    gemm_kernel<<<ggrid, 128, SMEM_BYTES>>>(latents, W[0], bb[0], bufA, 1, 0.0f);
    gemm_kernel<<<ggrid, 128, SMEM_BYTES>>>(bufA,    W[1], bb[1], bufB, 1, 0.0f);
    gemm_kernel<<<ggrid, 128, SMEM_BYTES>>>(bufB,    W[2], bb[2], bufA, 1, 0.0f);
    gemm_kernel<<<ggrid, 128, SMEM_BYTES>>>(bufA,    W[3], bb[3], bufB, 1, 0.0f);
    gemm_kernel<<<ggrid, 128, SMEM_BYTES>>>(bufB,    W[4], bb[4], bufA, 1, 0.0f);
    gemm_kernel<<<ggrid, 128, SMEM_BYTES>>>(bufA, WpT, bp, mu, 0, 0.5f);

    tail_kernel<<<BSZ, 256>>>(realPoints, predMu, predScale, eps, out);
}

// round 6
// speedup vs baseline: 1.3646x; 1.3646x over previous
#include <cuda_runtime.h>
#include <cuda_fp16.h>
#include <math.h>
#include <stdint.h>

// Problem constants
#define BSZ   1024
#define NPTS  128
#define LOG2PI_F 1.8378770664093453f
#define LOG1P_HALF 0.40546510810816438f

// Output layout offsets
#define OFF_SAMPLED 0
#define OFF_GEN     524288
#define OFF_REAL    655360
#define OFF_LOSSA   786432
#define OFF_LOSSB   917504

// split scales: a = h + l'*2^-11 + q'*2^-22
#define SC_L 4.8828125e-4f            // 2^-11
#define SC_Q 2.384185791015625e-7f    // 2^-22

#define ACT_PLANE 262144              // halves per activation plane (1024*256)
#define W_LAYER   (3 * 256 * 256)     // halves per layer of split weights

// Layer GEMM smem (bytes): A 3 planes of 64x264 fp16, B 3 planes of 32x264 fp16
#define A_PLANE_B 33792               // 64*264*2
#define B_PLANE_B 16896               // 32*264*2
#define SM_B_OFF  101376              // 3*A_PLANE_B
#define SM_BIAS   152064              // 3*A+3*B
#define SM_TOTAL  152192              // + 32 floats

// Scratch
__device__ __half g_Act[2][3 * ACT_PLANE];     // ping-pong split activations
__device__ __half g_Wsplit[6 * W_LAYER];       // [L][split][n][k]
__device__ float  g_mu[BSZ * 256];

// ---------------------------------------------------------------------------
// helpers
// ---------------------------------------------------------------------------
__device__ __forceinline__ uint32_t cvta_smem(const void* p) {
    uint32_t a;
    asm("{ .reg .u64 t; cvta.to.shared.u64 t, %1; cvt.u32.u64 %0, t; }"
        : "=r"(a) : "l"(p));
    return a;
}
__device__ __forceinline__ void ldsm4(uint32_t* r, uint32_t addr) {
    asm volatile("ldmatrix.sync.aligned.m8n8.x4.shared.b16 {%0,%1,%2,%3}, [%4];"
                 : "=r"(r[0]), "=r"(r[1]), "=r"(r[2]), "=r"(r[3]) : "r"(addr));
}
__device__ __forceinline__ void mma16816(float* d, const uint32_t* a, const uint32_t* b) {
    asm("mma.sync.aligned.m16n8k16.row.col.f32.f16.f16.f32 "
        "{%0,%1,%2,%3}, {%4,%5,%6,%7}, {%8,%9}, {%0,%1,%2,%3};"
        : "+f"(d[0]), "+f"(d[1]), "+f"(d[2]), "+f"(d[3])
        : "r"(a[0]), "r"(a[1]), "r"(a[2]), "r"(a[3]), "r"(b[0]), "r"(b[1]));
}
// exact 3-way fp16 split, low terms rescaled to fp16-normal range
__device__ __forceinline__ void split3(float a, __half& h, __half& l, __half& q) {
    h = __float2half_rn(a);
    float r1 = a - __half2float(h);
    l = __float2half_rn(r1 * 2048.0f);
    float r2 = r1 - __half2float(l) * SC_L;
    q = __float2half_rn(r2 * 4194304.0f);
}
__device__ __forceinline__ uint32_t pack2(__half a, __half b) {
    __half2 h = __halves2half2(a, b);
    return *(uint32_t*)&h;
}

// ---------------------------------------------------------------------------
// prep: g_Wsplit[L][s][n][k] fp16 3-split of W_L^T (L=5 is Wp reshaped)
// ---------------------------------------------------------------------------
__global__ __launch_bounds__(256) void prep_weights(
    const float* __restrict__ W0, const float* __restrict__ W1,
    const float* __restrict__ W2, const float* __restrict__ W3,
    const float* __restrict__ W4, const float* __restrict__ Wp)
{
    __shared__ float stage[256][9];
    const int L  = blockIdx.y;
    const int n0 = blockIdx.x * 8;
    const int t  = threadIdx.x;

    {
        const int k = t;
        if (L < 5) {
            const float* W = (L == 0) ? W0 : (L == 1) ? W1 : (L == 2) ? W2
                           : (L == 3) ? W3 : W4;
            float4 v0 = *(const float4*)&W[k * 256 + n0];
            float4 v1 = *(const float4*)&W[k * 256 + n0 + 4];
            stage[k][0] = v0.x; stage[k][1] = v0.y; stage[k][2] = v0.z; stage[k][3] = v0.w;
            stage[k][4] = v1.x; stage[k][5] = v1.y; stage[k][6] = v1.z; stage[k][7] = v1.w;
        } else {
#pragma unroll
            for (int j = 0; j < 8; j++) {
                int n = n0 + j;
                stage[k][j] = Wp[(n >> 1) * 512 + k * 2 + (n & 1)];
            }
        }
    }
    __syncthreads();
    {
        const int nl = t >> 5;
        const int k0 = (t & 31) * 8;
        __half h[8], l[8], q[8];
#pragma unroll
        for (int i = 0; i < 8; i++)
            split3(stage[k0 + i][nl], h[i], l[i], q[i]);
        const int n = n0 + nl;
        __half* base = g_Wsplit + (size_t)L * W_LAYER;
        uint4 v;
        v.x = pack2(h[0], h[1]); v.y = pack2(h[2], h[3]);
        v.z = pack2(h[4], h[5]); v.w = pack2(h[6], h[7]);
        *(uint4*)(base + (0 * 256 + n) * 256 + k0) = v;
        v.x = pack2(l[0], l[1]); v.y = pack2(l[2], l[3]);
        v.z = pack2(l[4], l[5]); v.w = pack2(l[6], l[7]);
        *(uint4*)(base + (1 * 256 + n) * 256 + k0) = v;
        v.x = pack2(q[0], q[1]); v.y = pack2(q[2], q[3]);
        v.z = pack2(q[4], q[5]); v.w = pack2(q[6], q[7]);
        *(uint4*)(base + (2 * 256 + n) * 256 + k0) = v;
    }
}

// ---------------------------------------------------------------------------
// prep latents: fp32 [1024][256] -> 3 fp16 split planes
// ---------------------------------------------------------------------------
__global__ __launch_bounds__(256) void prep_latents(
    const float* __restrict__ L, __half* __restrict__ out)
{
    int idx = (blockIdx.x * 256 + threadIdx.x) * 4;
    float4 v = *(const float4*)(L + idx);
    __half h[4], l[4], q[4];
    split3(v.x, h[0], l[0], q[0]);
    split3(v.y, h[1], l[1], q[1]);
    split3(v.z, h[2], l[2], q[2]);
    split3(v.w, h[3], l[3], q[3]);
    uint2 u;
    u.x = pack2(h[0], h[1]); u.y = pack2(h[2], h[3]);
    *(uint2*)(out + idx) = u;
    u.x = pack2(l[0], l[1]); u.y = pack2(l[2], l[3]);
    *(uint2*)(out + ACT_PLANE + idx) = u;
    u.x = pack2(q[0], q[1]); u.y = pack2(q[2], q[3]);
    *(uint2*)(out + 2 * ACT_PLANE + idx) = u;
}

// ---------------------------------------------------------------------------
// layer: Y[1024,256] = (isMu? : relu)(X @ W + bias (+0.5 if mu))
// X as 3 fp16 split planes; W as 3 fp16 split planes [n][k].
// CTA 64x32, 128 thr (4 warps, 2x2 of 32x16 warp tiles), full K=256 in smem.
// Grid (8 n-tiles, 16 m-tiles) = 128 CTAs.
// 6 HMMA products -> 3 accumulator sets, recombined in epilogue.
// ---------------------------------------------------------------------------
__global__ __launch_bounds__(128) void layer_kernel(
    const __half* __restrict__ Ain, const __half* __restrict__ Wsp,
    const float* __restrict__ bias, __half* __restrict__ Aout,
    float* __restrict__ muOut, int isMu)
{
    extern __shared__ char smem[];
    const uint32_t sbase = cvta_smem(smem);
    float* sBias = (float*)(smem + SM_BIAS);

    const int t    = threadIdx.x;
    const int lane = t & 31;
    const int wid  = t >> 5;
    const int n0   = blockIdx.x * 32;
    const int m0   = blockIdx.y * 64;
    const int wm   = (wid & 1) * 32;
    const int wn   = (wid >> 1) * 16;

    // ---- prologue: stage A (64x256x3) and B (32x256x3) fp16, 528B row pitch ----
#pragma unroll
    for (int i = 0; i < 48; i++) {           // A: 6144 16B-chunks
        int idx = i * 128 + t;
        int s = idx >> 11;
        int r = (idx >> 5) & 63;
        int c = idx & 31;
        uint4 v = *(const uint4*)(Ain + s * ACT_PLANE + ((m0 + r) << 8) + (c << 3));
        *(uint4*)(smem + s * A_PLANE_B + r * 528 + c * 16) = v;
    }
#pragma unroll
    for (int i = 0; i < 24; i++) {           // B: 3072 16B-chunks
        int idx = i * 128 + t;
        int s = idx >> 10;
        int r = (idx >> 5) & 31;
        int c = idx & 31;
        uint4 v = *(const uint4*)(Wsp + ((s * 256 + n0 + r) << 8) + (c << 3));
        *(uint4*)(smem + SM_B_OFF + s * B_PLANE_B + r * 528 + c * 16) = v;
    }
    if (t < 32) sBias[t] = bias[n0 + t];
    __syncthreads();

    // ldmatrix base addresses
    const int rA = wm + (lane & 15);
    const uint32_t aAddr = sbase + rA * 528 + (lane >> 4) * 16;
    const int rB = wn + ((lane >> 4) << 3) + (lane & 7);
    const uint32_t bAddr = sbase + SM_B_OFF + rB * 528 + (((lane >> 3) & 1) << 4);

    float D0[2][2][4] = {}, D1[2][2][4] = {}, D2[2][2][4] = {};

#pragma unroll
    for (int ks = 0; ks < 16; ks++) {
        uint32_t A[3][2][4], B[3][4];
#pragma unroll
        for (int s = 0; s < 3; s++) {
            ldsm4(A[s][0], aAddr + s * A_PLANE_B + ks * 32);
            ldsm4(A[s][1], aAddr + s * A_PLANE_B + 8448 + ks * 32);  // +16 rows
            ldsm4(B[s],    bAddr + s * B_PLANE_B + ks * 32);
        }
#pragma unroll
        for (int mi = 0; mi < 2; mi++)
#pragma unroll
            for (int ni = 0; ni < 2; ni++) {
                const uint32_t* bh = &B[0][ni * 2];
                const uint32_t* bl = &B[1][ni * 2];
                const uint32_t* bq = &B[2][ni * 2];
                mma16816(D0[mi][ni], A[0][mi], bh);
                mma16816(D1[mi][ni], A[0][mi], bl);
                mma16816(D1[mi][ni], A[1][mi], bh);
                mma16816(D2[mi][ni], A[0][mi], bq);
                mma16816(D2[mi][ni], A[1][mi], bl);
                mma16816(D2[mi][ni], A[2][mi], bh);
            }
    }

    // ---- epilogue ----
    const int crow  = lane >> 2;
    const int ccol2 = (lane & 3) * 2;
#pragma unroll
    for (int mi = 0; mi < 2; mi++)
#pragma unroll
        for (int ni = 0; ni < 2; ni++) {
            int nl = wn + ni * 8 + ccol2;
            int n  = n0 + nl;
            float b0v = sBias[nl], b1v = sBias[nl + 1];
#pragma unroll
            for (int hh = 0; hh < 2; hh++) {
                float d0 = D0[mi][ni][hh * 2] +
                           fmaf(D2[mi][ni][hh * 2], SC_Q, D1[mi][ni][hh * 2] * SC_L);
                float d1 = D0[mi][ni][hh * 2 + 1] +
                           fmaf(D2[mi][ni][hh * 2 + 1], SC_Q, D1[mi][ni][hh * 2 + 1] * SC_L);
                int m = m0 + wm + mi * 16 + crow + hh * 8;
                if (!isMu) {
                    float y0 = fmaxf(d0 + b0v, 0.0f);
                    float y1 = fmaxf(d1 + b1v, 0.0f);
                    __half h0, l0, q0, h1, l1, q1;
                    split3(y0, h0, l0, q0);
                    split3(y1, h1, l1, q1);
                    *(uint32_t*)(Aout + m * 256 + n)                 = pack2(h0, h1);
                    *(uint32_t*)(Aout + ACT_PLANE + m * 256 + n)     = pack2(l0, l1);
                    *(uint32_t*)(Aout + 2 * ACT_PLANE + m * 256 + n) = pack2(q0, q1);
                } else {
                    float2 v;
                    v.x = d0 + b0v + 0.5f;
                    v.y = d1 + b1v + 0.5f;
                    *(float2*)(muOut + m * 256 + n) = v;
                }
            }
        }
}

// ---------------------------------------------------------------------------
// Fused tail: one CTA per batch row b; thread = (n, s), tid = 2n + s.
// ---------------------------------------------------------------------------
__global__ __launch_bounds__(256) void tail_kernel(
    const float* __restrict__ realPoints,
    const float* __restrict__ predMu,
    const float* __restrict__ predScale,
    const float* __restrict__ eps,
    float* __restrict__ out)
{
    const int b = blockIdx.x;
    __shared__ float mu_s[256];
    __shared__ float am[128];
    __shared__ float cm[128];
    __shared__ float sc[7];

    const int tid = threadIdx.x;
    mu_s[tid] = g_mu[b * 256 + tid];
    if (tid < 128) {
        float dev = 0.001f + (float)tid * (0.009f / 127.0f);
        am[tid] = -0.5f / (dev * dev);
        cm[tid] = -2.0f * logf(dev) - LOG2PI_F;
    }
    if (tid == 0) {
        sc[0] = realPoints[b * 2];
        sc[1] = realPoints[b * 2 + 1];
        sc[2] = predMu[b * 2];
        sc[3] = predMu[b * 2 + 1];
        float p0 = predScale[b * 2], p1 = predScale[b * 2 + 1];
        sc[4] = 1.0f / p0;
        sc[5] = 1.0f / p1;
        sc[6] = logf(p0) + logf(p1);
    }
    __syncthreads();

    const int n = tid >> 1;
    const int s = tid & 1;

    const float mu0 = mu_s[2 * n];
    const float mu1 = mu_s[2 * n + 1];
    const float dev = 0.001f + (float)n * (0.009f / 127.0f);

    const int eoff = s * (BSZ * NPTS * 2) + (b * NPTS + n) * 2;
    const float e0 = eps[eoff];
    const float e1 = eps[eoff + 1];
    const float s0 = fmaf(dev, e0, mu0);
    const float s1 = fmaf(dev, e1, mu1);

    {
        long so = ((long)(s * NPTS + n) * BSZ + b) * 2;
        out[OFF_SAMPLED + so]     = s0;
        out[OFF_SAMPLED + so + 1] = s1;
    }

    float sumexp = 0.0f;
    float en = 0.0f;
#pragma unroll 4
    for (int m = 0; m < 128; m++) {
        float d0 = s0 - mu_s[2 * m];
        float d1 = s1 - mu_s[2 * m + 1];
        float ss = fmaf(d0, d0, d1 * d1);
        float lb = fmaf(ss, am[m], cm[m]);
        float e  = __expf(lb);
        sumexp += e;
        if (m == n) en = e;
    }
    float diag = en / sumexp;
    float lbv  = 1.0f - diag;
    out[OFF_LOSSB + b * 256 + tid] = lbv * lbv;

    float z0 = (s0 - sc[2]) * sc[4];
    float z1 = (s1 - sc[3]) * sc[5];
    float lp = fmaf(-0.5f, fmaf(z0, z0, z1 * z1), -sc[6] - LOG2PI_F);
    float gl  = 1.0f / (1.0f + __expf(-lp));
    float sgn = 1.0f / (1.0f + __expf(lp));
    float tA  = LOG1P_HALF - log1pf(sgn);
    tA *= tA;

    float gl_o = __shfl_xor_sync(0xffffffffu, gl, 1);
    float tA_o = __shfl_xor_sync(0xffffffffu, tA, 1);

    if (s == 0) {
        float glm   = 0.5f * (gl + gl_o);
        float lossA = 0.5f * (tA + tA_o);
        float dr0 = sc[0] - mu0;
        float dr1 = sc[1] - mu1;
        float ssr = fmaf(dr0, dr0, dr1 * dr1);
        float rlp = fmaf(ssr, am[n], cm[n]);
        float rl  = 1.0f / (1.0f + __expf(-rlp));
        out[OFF_REAL  + b * NPTS + n] = rl;
        out[OFF_LOSSA + b * NPTS + n] = lossA;
        out[OFF_GEN   + b * NPTS + n] = glm * (1.0f - rl);
    }
}

// ---------------------------------------------------------------------------
extern "C" void kernel_launch(void* const* d_in, const int* in_sizes, int n_in,
                              void* d_out, int out_size) {
    const float* latents    = (const float*)d_in[0];
    const float* realPoints = (const float*)d_in[1];
    const float* predMu     = (const float*)d_in[2];
    const float* predScale  = (const float*)d_in[3];
    const float* eps        = (const float*)d_in[4];
    const float* W[5]  = {(const float*)d_in[5],  (const float*)d_in[7],
                          (const float*)d_in[9],  (const float*)d_in[11],
                          (const float*)d_in[13]};
    const float* bb[5] = {(const float*)d_in[6],  (const float*)d_in[8],
                          (const float*)d_in[10], (const float*)d_in[12],
                          (const float*)d_in[14]};
    const float* bp = (const float*)d_in[16];
    float* out = (float*)d_out;

    __half *gA, *gW;
    float* mu;
    cudaGetSymbolAddress((void**)&gA, g_Act);
    cudaGetSymbolAddress((void**)&gW, g_Wsplit);
    cudaGetSymbolAddress((void**)&mu, g_mu);
    __half* A0 = gA;
    __half* A1 = gA + 3 * (size_t)ACT_PLANE;

    cudaFuncSetAttribute(layer_kernel,
                         cudaFuncAttributeMaxDynamicSharedMemorySize, SM_TOTAL);

    prep_weights<<<dim3(32, 6), 256>>>(W[0], W[1], W[2], W[3], W[4],
                                       (const float*)d_in[15]);
    prep_latents<<<256, 256>>>(latents, A0);

    dim3 grid(8, 16);
    layer_kernel<<<grid, 128, SM_TOTAL>>>(A0, gW + 0 * (size_t)W_LAYER, bb[0], A1, mu, 0);
    layer_kernel<<<grid, 128, SM_TOTAL>>>(A1, gW + 1 * (size_t)W_LAYER, bb[1], A0, mu, 0);
    layer_kernel<<<grid, 128, SM_TOTAL>>>(A0, gW + 2 * (size_t)W_LAYER, bb[2], A1, mu, 0);
    layer_kernel<<<grid, 128, SM_TOTAL>>>(A1, gW + 3 * (size_t)W_LAYER, bb[3], A0, mu, 0);
    layer_kernel<<<grid, 128, SM_TOTAL>>>(A0, gW + 4 * (size_t)W_LAYER, bb[4], A1, mu, 0);
    layer_kernel<<<grid, 128, SM_TOTAL>>>(A1, gW + 5 * (size_t)W_LAYER, bp, A0, mu, 1);

    tail_kernel<<<BSZ, 256>>>(realPoints, predMu, predScale, eps, out);
}

// round 7
// speedup vs baseline: 1.7636x; 1.2924x over previous
#include <cuda_runtime.h>
#include <cuda_fp16.h>
#include <math.h>
#include <stdint.h>

// Problem constants
#define BSZ   1024
#define NPTS  128
#define LOG2PI_F 1.8378770664093453f
#define LOG1P_HALF 0.40546510810816438f

// Output layout offsets
#define OFF_SAMPLED 0
#define OFF_GEN     524288
#define OFF_REAL    655360
#define OFF_LOSSA   786432
#define OFF_LOSSB   917504

// split scales: a = h + l'*2^-11 + q'*2^-22
#define SC_L 4.8828125e-4f            // 2^-11
#define SC_Q 2.384185791015625e-7f    // 2^-22

#define ACT_PLANE 262144              // halves per activation plane (1024*256)
#define W_LAYER   (3 * 256 * 256)     // halves per layer of split weights

// Layer smem: A 3 planes of 32x256 fp16 (16KB each), B 3 planes same, + bias
#define SM_PLANE  16384
#define SM_B_OFF  49152
#define SM_BIAS   98304
#define SM_TOTAL  98432

// Scratch
__device__ __half g_Act[2][3 * ACT_PLANE];     // ping-pong split activations
__device__ __half g_Wsplit[6 * W_LAYER];       // [L][split][n][k]
__device__ float  g_mu[BSZ * 256];

// ---------------------------------------------------------------------------
// helpers
// ---------------------------------------------------------------------------
__device__ __forceinline__ uint32_t cvta_smem(const void* p) {
    uint32_t a;
    asm("{ .reg .u64 t; cvta.to.shared.u64 t, %1; cvt.u32.u64 %0, t; }"
        : "=r"(a) : "l"(p));
    return a;
}
__device__ __forceinline__ void cp16(uint32_t saddr, const void* gaddr) {
    asm volatile("cp.async.cg.shared.global [%0], [%1], 16;"
                 :: "r"(saddr), "l"(gaddr));
}
__device__ __forceinline__ void cp_wait_all() {
    asm volatile("cp.async.commit_group;" ::: "memory");
    asm volatile("cp.async.wait_group 0;" ::: "memory");
}
__device__ __forceinline__ void ldsm4(uint32_t* r, uint32_t addr) {
    asm volatile("ldmatrix.sync.aligned.m8n8.x4.shared.b16 {%0,%1,%2,%3}, [%4];"
                 : "=r"(r[0]), "=r"(r[1]), "=r"(r[2]), "=r"(r[3]) : "r"(addr));
}
__device__ __forceinline__ void mma16816(float* d, const uint32_t* a, const uint32_t* b) {
    asm("mma.sync.aligned.m16n8k16.row.col.f32.f16.f16.f32 "
        "{%0,%1,%2,%3}, {%4,%5,%6,%7}, {%8,%9}, {%0,%1,%2,%3};"
        : "+f"(d[0]), "+f"(d[1]), "+f"(d[2]), "+f"(d[3])
        : "r"(a[0]), "r"(a[1]), "r"(a[2]), "r"(a[3]), "r"(b[0]), "r"(b[1]));
}
// exact 3-way fp16 split, low terms rescaled to fp16-normal range
__device__ __forceinline__ void split3(float a, __half& h, __half& l, __half& q) {
    h = __float2half_rn(a);
    float r1 = a - __half2float(h);
    l = __float2half_rn(r1 * 2048.0f);
    float r2 = r1 - __half2float(l) * SC_L;
    q = __float2half_rn(r2 * 4194304.0f);
}
__device__ __forceinline__ uint32_t pack2(__half a, __half b) {
    __half2 h = __halves2half2(a, b);
    return *(uint32_t*)&h;
}
// 16B-chunk XOR swizzle within 128B groups: logical chunk c, row r
__device__ __forceinline__ uint32_t swz(uint32_t c, uint32_t r) {
    return (c & 24u) | ((c ^ r) & 7u);
}

// ---------------------------------------------------------------------------
// prep: g_Wsplit[L][s][n][k] fp16 3-split of W_L^T (L=5 is Wp reshaped)
// ---------------------------------------------------------------------------
__global__ __launch_bounds__(256) void prep_weights(
    const float* __restrict__ W0, const float* __restrict__ W1,
    const float* __restrict__ W2, const float* __restrict__ W3,
    const float* __restrict__ W4, const float* __restrict__ Wp)
{
    __shared__ float stage[256][9];
    const int L  = blockIdx.y;
    const int n0 = blockIdx.x * 8;
    const int t  = threadIdx.x;

    {
        const int k = t;
        if (L < 5) {
            const float* W = (L == 0) ? W0 : (L == 1) ? W1 : (L == 2) ? W2
                           : (L == 3) ? W3 : W4;
            float4 v0 = *(const float4*)&W[k * 256 + n0];
            float4 v1 = *(const float4*)&W[k * 256 + n0 + 4];
            stage[k][0] = v0.x; stage[k][1] = v0.y; stage[k][2] = v0.z; stage[k][3] = v0.w;
            stage[k][4] = v1.x; stage[k][5] = v1.y; stage[k][6] = v1.z; stage[k][7] = v1.w;
        } else {
#pragma unroll
            for (int j = 0; j < 8; j++) {
                int n = n0 + j;
                stage[k][j] = Wp[(n >> 1) * 512 + k * 2 + (n & 1)];
            }
        }
    }
    __syncthreads();
    {
        const int nl = t >> 5;
        const int k0 = (t & 31) * 8;
        __half h[8], l[8], q[8];
#pragma unroll
        for (int i = 0; i < 8; i++)
            split3(stage[k0 + i][nl], h[i], l[i], q[i]);
        const int n = n0 + nl;
        __half* base = g_Wsplit + (size_t)L * W_LAYER;
        uint4 v;
        v.x = pack2(h[0], h[1]); v.y = pack2(h[2], h[3]);
        v.z = pack2(h[4], h[5]); v.w = pack2(h[6], h[7]);
        *(uint4*)(base + (0 * 256 + n) * 256 + k0) = v;
        v.x = pack2(l[0], l[1]); v.y = pack2(l[2], l[3]);
        v.z = pack2(l[4], l[5]); v.w = pack2(l[6], l[7]);
        *(uint4*)(base + (1 * 256 + n) * 256 + k0) = v;
        v.x = pack2(q[0], q[1]); v.y = pack2(q[2], q[3]);
        v.z = pack2(q[4], q[5]); v.w = pack2(q[6], q[7]);
        *(uint4*)(base + (2 * 256 + n) * 256 + k0) = v;
    }
}

// ---------------------------------------------------------------------------
// prep latents: fp32 [1024][256] -> 3 fp16 split planes
// ---------------------------------------------------------------------------
__global__ __launch_bounds__(256) void prep_latents(
    const float* __restrict__ L, __half* __restrict__ out)
{
    int idx = (blockIdx.x * 256 + threadIdx.x) * 4;
    float4 v = *(const float4*)(L + idx);
    __half h[4], l[4], q[4];
    split3(v.x, h[0], l[0], q[0]);
    split3(v.y, h[1], l[1], q[1]);
    split3(v.z, h[2], l[2], q[2]);
    split3(v.w, h[3], l[3], q[3]);
    uint2 u;
    u.x = pack2(h[0], h[1]); u.y = pack2(h[2], h[3]);
    *(uint2*)(out + idx) = u;
    u.x = pack2(l[0], l[1]); u.y = pack2(l[2], l[3]);
    *(uint2*)(out + ACT_PLANE + idx) = u;
    u.x = pack2(q[0], q[1]); u.y = pack2(q[2], q[3]);
    *(uint2*)(out + 2 * ACT_PLANE + idx) = u;
}

// ---------------------------------------------------------------------------
// layer: Y[1024,256] = (isMu? : relu)(X @ W + bias (+0.5 if mu))
// Tile 32x32, 128 thr (2x2 warps of 16x16), full K=256 staged via cp.async.
// Grid (8 n-tiles, 32 m-tiles) = 256 CTAs, 2 CTAs/SM.
// ---------------------------------------------------------------------------
__global__ __launch_bounds__(128) void layer_kernel(
    const __half* __restrict__ Ain, const __half* __restrict__ Wsp,
    const float* __restrict__ bias, __half* __restrict__ Aout,
    float* __restrict__ muOut, int isMu)
{
    extern __shared__ char smem[];
    const uint32_t sbase = cvta_smem(smem);
    float* sBias = (float*)(smem + SM_BIAS);

    const int t    = threadIdx.x;
    const int lane = t & 31;
    const int wid  = t >> 5;
    const int n0   = blockIdx.x * 32;
    const int m0   = blockIdx.y * 32;
    const int wm   = (wid & 1) * 16;
    const int wn   = (wid >> 1) * 16;

    // ---- prologue: cp.async A (3x32x256) and B (3x32x256), swizzled ----
#pragma unroll
    for (int i = 0; i < 24; i++) {           // A: 3072 chunks
        int id = i * 128 + t;
        int s = id >> 10;
        int r = (id >> 5) & 31;
        int c = id & 31;
        const void* g = Ain + (size_t)s * ACT_PLANE + ((m0 + r) << 8) + (c << 3);
        cp16(sbase + s * SM_PLANE + (r << 9) + (swz(c, r & 7) << 4), g);
    }
#pragma unroll
    for (int i = 0; i < 24; i++) {           // B: 3072 chunks
        int id = i * 128 + t;
        int s = id >> 10;
        int r = (id >> 5) & 31;
        int c = id & 31;
        const void* g = Wsp + (((s << 8) + n0 + r) << 8) + (c << 3);
        cp16(sbase + SM_B_OFF + s * SM_PLANE + (r << 9) + (swz(c, r & 7) << 4), g);
    }
    if (t < 32) sBias[t] = bias[n0 + t];
    cp_wait_all();
    __syncthreads();

    // ldmatrix per-lane bases
    const uint32_t rowA  = wm + (lane & 15);
    const uint32_t aRowB = sbase + rowA * 512;
    const uint32_t axr   = rowA & 7;
    const uint32_t ahi   = lane >> 4;          // chunk offset 0/1
    const uint32_t rowB  = wn + ((lane >> 4) << 3) + (lane & 7);
    const uint32_t bRowB = sbase + SM_B_OFF + rowB * 512;
    const uint32_t bxr   = rowB & 7;
    const uint32_t bhi   = (lane >> 3) & 1;

    float D0[2][4] = {}, D1[2][4] = {}, D2[2][4] = {};

#pragma unroll
    for (int ks = 0; ks < 16; ks++) {
        uint32_t A[3][4], B[3][4];
        uint32_t ca = swz(ks * 2 + ahi, axr) << 4;
        uint32_t cb = swz(ks * 2 + bhi, bxr) << 4;
#pragma unroll
        for (int s = 0; s < 3; s++) {
            ldsm4(A[s], aRowB + s * SM_PLANE + ca);
            ldsm4(B[s], bRowB + s * SM_PLANE + cb);
        }
#pragma unroll
        for (int ni = 0; ni < 2; ni++) {
            const uint32_t* bh = &B[0][ni * 2];
            const uint32_t* bl = &B[1][ni * 2];
            const uint32_t* bq = &B[2][ni * 2];
            mma16816(D0[ni], A[0], bh);
            mma16816(D1[ni], A[0], bl);
            mma16816(D1[ni], A[1], bh);
            mma16816(D2[ni], A[0], bq);
            mma16816(D2[ni], A[1], bl);
            mma16816(D2[ni], A[2], bh);
        }
    }

    // ---- epilogue ----
    const int crow  = lane >> 2;
    const int ccol2 = (lane & 3) * 2;
#pragma unroll
    for (int ni = 0; ni < 2; ni++) {
        int nl = wn + ni * 8 + ccol2;
        int n  = n0 + nl;
        float b0v = sBias[nl], b1v = sBias[nl + 1];
#pragma unroll
        for (int hh = 0; hh < 2; hh++) {
            float d0 = D0[ni][hh * 2] +
                       fmaf(D2[ni][hh * 2], SC_Q, D1[ni][hh * 2] * SC_L);
            float d1 = D0[ni][hh * 2 + 1] +
                       fmaf(D2[ni][hh * 2 + 1], SC_Q, D1[ni][hh * 2 + 1] * SC_L);
            int m = m0 + wm + crow + hh * 8;
            if (!isMu) {
                float y0 = fmaxf(d0 + b0v, 0.0f);
                float y1 = fmaxf(d1 + b1v, 0.0f);
                __half h0, l0, q0, h1, l1, q1;
                split3(y0, h0, l0, q0);
                split3(y1, h1, l1, q1);
                *(uint32_t*)(Aout + m * 256 + n)                 = pack2(h0, h1);
                *(uint32_t*)(Aout + ACT_PLANE + m * 256 + n)     = pack2(l0, l1);
                *(uint32_t*)(Aout + 2 * ACT_PLANE + m * 256 + n) = pack2(q0, q1);
            } else {
                float2 v;
                v.x = d0 + b0v + 0.5f;
                v.y = d1 + b1v + 0.5f;
                *(float2*)(muOut + m * 256 + n) = v;
            }
        }
    }
}

// ---------------------------------------------------------------------------
// Fused tail: one CTA per batch row b; thread = (n, s), tid = 2n + s.
// ---------------------------------------------------------------------------
__global__ __launch_bounds__(256) void tail_kernel(
    const float* __restrict__ realPoints,
    const float* __restrict__ predMu,
    const float* __restrict__ predScale,
    const float* __restrict__ eps,
    float* __restrict__ out)
{
    const int b = blockIdx.x;
    __shared__ float mu_s[256];
    __shared__ float am[128];
    __shared__ float cm[128];
    __shared__ float sc[7];

    const int tid = threadIdx.x;
    mu_s[tid] = g_mu[b * 256 + tid];
    if (tid < 128) {
        float dev = 0.001f + (float)tid * (0.009f / 127.0f);
        am[tid] = -0.5f / (dev * dev);
        cm[tid] = -2.0f * logf(dev) - LOG2PI_F;
    }
    if (tid == 0) {
        sc[0] = realPoints[b * 2];
        sc[1] = realPoints[b * 2 + 1];
        sc[2] = predMu[b * 2];
        sc[3] = predMu[b * 2 + 1];
        float p0 = predScale[b * 2], p1 = predScale[b * 2 + 1];
        sc[4] = 1.0f / p0;
        sc[5] = 1.0f / p1;
        sc[6] = logf(p0) + logf(p1);
    }
    __syncthreads();

    const int n = tid >> 1;
    const int s = tid & 1;

    const float mu0 = mu_s[2 * n];
    const float mu1 = mu_s[2 * n + 1];
    const float dev = 0.001f + (float)n * (0.009f / 127.0f);

    const int eoff = s * (BSZ * NPTS * 2) + (b * NPTS + n) * 2;
    const float e0 = eps[eoff];
    const float e1 = eps[eoff + 1];
    const float s0 = fmaf(dev, e0, mu0);
    const float s1 = fmaf(dev, e1, mu1);

    {
        long so = ((long)(s * NPTS + n) * BSZ + b) * 2;
        out[OFF_SAMPLED + so]     = s0;
        out[OFF_SAMPLED + so + 1] = s1;
    }

    float sumexp = 0.0f;
    float en = 0.0f;
#pragma unroll 4
    for (int m = 0; m < 128; m++) {
        float d0 = s0 - mu_s[2 * m];
        float d1 = s1 - mu_s[2 * m + 1];
        float ss = fmaf(d0, d0, d1 * d1);
        float lb = fmaf(ss, am[m], cm[m]);
        float e  = __expf(lb);
        sumexp += e;
        if (m == n) en = e;
    }
    float diag = en / sumexp;
    float lbv  = 1.0f - diag;
    out[OFF_LOSSB + b * 256 + tid] = lbv * lbv;

    float z0 = (s0 - sc[2]) * sc[4];
    float z1 = (s1 - sc[3]) * sc[5];
    float lp = fmaf(-0.5f, fmaf(z0, z0, z1 * z1), -sc[6] - LOG2PI_F);
    float gl  = 1.0f / (1.0f + __expf(-lp));
    float sgn = 1.0f / (1.0f + __expf(lp));
    float tA  = LOG1P_HALF - log1pf(sgn);
    tA *= tA;

    float gl_o = __shfl_xor_sync(0xffffffffu, gl, 1);
    float tA_o = __shfl_xor_sync(0xffffffffu, tA, 1);

    if (s == 0) {
        float glm   = 0.5f * (gl + gl_o);
        float lossA = 0.5f * (tA + tA_o);
        float dr0 = sc[0] - mu0;
        float dr1 = sc[1] - mu1;
        float ssr = fmaf(dr0, dr0, dr1 * dr1);
        float rlp = fmaf(ssr, am[n], cm[n]);
        float rl  = 1.0f / (1.0f + __expf(-rlp));
        out[OFF_REAL  + b * NPTS + n] = rl;
        out[OFF_LOSSA + b * NPTS + n] = lossA;
        out[OFF_GEN   + b * NPTS + n] = glm * (1.0f - rl);
    }
}

// ---------------------------------------------------------------------------
extern "C" void kernel_launch(void* const* d_in, const int* in_sizes, int n_in,
                              void* d_out, int out_size) {
    const float* latents    = (const float*)d_in[0];
    const float* realPoints = (const float*)d_in[1];
    const float* predMu     = (const float*)d_in[2];
    const float* predScale  = (const float*)d_in[3];
    const float* eps        = (const float*)d_in[4];
    const float* W[5]  = {(const float*)d_in[5],  (const float*)d_in[7],
                          (const float*)d_in[9],  (const float*)d_in[11],
                          (const float*)d_in[13]};
    const float* bb[5] = {(const float*)d_in[6],  (const float*)d_in[8],
                          (const float*)d_in[10], (const float*)d_in[12],
                          (const float*)d_in[14]};
    const float* bp = (const float*)d_in[16];
    float* out = (float*)d_out;

    __half *gA, *gW;
    float* mu;
    cudaGetSymbolAddress((void**)&gA, g_Act);
    cudaGetSymbolAddress((void**)&gW, g_Wsplit);
    cudaGetSymbolAddress((void**)&mu, g_mu);
    __half* A0 = gA;
    __half* A1 = gA + 3 * (size_t)ACT_PLANE;

    cudaFuncSetAttribute(layer_kernel,
                         cudaFuncAttributeMaxDynamicSharedMemorySize, SM_TOTAL);

    prep_weights<<<dim3(32, 6), 256>>>(W[0], W[1], W[2], W[3], W[4],
                                       (const float*)d_in[15]);
    prep_latents<<<256, 256>>>(latents, A0);

    dim3 grid(8, 32);
    layer_kernel<<<grid, 128, SM_TOTAL>>>(A0, gW + 0 * (size_t)W_LAYER, bb[0], A1, mu, 0);
    layer_kernel<<<grid, 128, SM_TOTAL>>>(A1, gW + 1 * (size_t)W_LAYER, bb[1], A0, mu, 0);
    layer_kernel<<<grid, 128, SM_TOTAL>>>(A0, gW + 2 * (size_t)W_LAYER, bb[2], A1, mu, 0);
    layer_kernel<<<grid, 128, SM_TOTAL>>>(A1, gW + 3 * (size_t)W_LAYER, bb[3], A0, mu, 0);
    layer_kernel<<<grid, 128, SM_TOTAL>>>(A0, gW + 4 * (size_t)W_LAYER, bb[4], A1, mu, 0);
    layer_kernel<<<grid, 128, SM_TOTAL>>>(A1, gW + 5 * (size_t)W_LAYER, bp, A0, mu, 1);

    tail_kernel<<<BSZ, 256>>>(realPoints, predMu, predScale, eps, out);
}

// round 8
// speedup vs baseline: 1.9795x; 1.1224x over previous
#include <cuda_runtime.h>
#include <cuda_fp16.h>
#include <math.h>
#include <stdint.h>

// Problem constants
#define BSZ   1024
#define NPTS  128
#define LOG2PI_F 1.8378770664093453f
#define LOG1P_HALF 0.40546510810816438f

// Output layout offsets
#define OFF_SAMPLED 0
#define OFF_GEN     524288
#define OFF_REAL    655360
#define OFF_LOSSA   786432
#define OFF_LOSSB   917504

// 2-way split: a = h + l'*2^-11  (residual ~2^-22)
#define SC_L 4.8828125e-4f            // 2^-11

#define ACT_PLANE 262144              // halves per activation plane (1024*256)
#define W_LAYER   (2 * 256 * 256)     // halves per layer of split weights

// Layer smem: A 2 planes of 32x256 fp16 (16KB each), B 2 planes, + bias
#define SM_PLANE  16384
#define SM_B_OFF  32768
#define SM_BIAS   65536
#define SM_TOTAL  65664

// Scratch
__device__ __half g_Act[2][2 * ACT_PLANE];     // ping-pong split activations
__device__ __half g_Wsplit[6 * W_LAYER];       // [L][split][n][k]
__device__ float  g_mu[BSZ * 256];

// ---------------------------------------------------------------------------
// helpers
// ---------------------------------------------------------------------------
__device__ __forceinline__ uint32_t cvta_smem(const void* p) {
    uint32_t a;
    asm("{ .reg .u64 t; cvta.to.shared.u64 t, %1; cvt.u32.u64 %0, t; }"
        : "=r"(a) : "l"(p));
    return a;
}
__device__ __forceinline__ void cp16(uint32_t saddr, const void* gaddr) {
    asm volatile("cp.async.cg.shared.global [%0], [%1], 16;"
                 :: "r"(saddr), "l"(gaddr));
}
__device__ __forceinline__ void cp_wait_all() {
    asm volatile("cp.async.commit_group;" ::: "memory");
    asm volatile("cp.async.wait_group 0;" ::: "memory");
}
__device__ __forceinline__ void ldsm4(uint32_t* r, uint32_t addr) {
    asm volatile("ldmatrix.sync.aligned.m8n8.x4.shared.b16 {%0,%1,%2,%3}, [%4];"
                 : "=r"(r[0]), "=r"(r[1]), "=r"(r[2]), "=r"(r[3]) : "r"(addr));
}
__device__ __forceinline__ void mma16816(float* d, const uint32_t* a, const uint32_t* b) {
    asm("mma.sync.aligned.m16n8k16.row.col.f32.f16.f16.f32 "
        "{%0,%1,%2,%3}, {%4,%5,%6,%7}, {%8,%9}, {%0,%1,%2,%3};"
        : "+f"(d[0]), "+f"(d[1]), "+f"(d[2]), "+f"(d[3])
        : "r"(a[0]), "r"(a[1]), "r"(a[2]), "r"(a[3]), "r"(b[0]), "r"(b[1]));
}
// 2-way fp16 split, low term rescaled to fp16-normal range
__device__ __forceinline__ void split2(float a, __half& h, __half& l) {
    h = __float2half_rn(a);
    float r1 = a - __half2float(h);
    l = __float2half_rn(r1 * 2048.0f);
}
__device__ __forceinline__ uint32_t pack2(__half a, __half b) {
    __half2 h = __halves2half2(a, b);
    return *(uint32_t*)&h;
}
// 16B-chunk XOR swizzle within 128B groups
__device__ __forceinline__ uint32_t swz(uint32_t c, uint32_t r) {
    return (c & 24u) | ((c ^ r) & 7u);
}

// ---------------------------------------------------------------------------
// prep: g_Wsplit[L][s][n][k] fp16 2-split of W_L^T (L=5 is Wp reshaped)
// ---------------------------------------------------------------------------
__global__ __launch_bounds__(256) void prep_weights(
    const float* __restrict__ W0, const float* __restrict__ W1,
    const float* __restrict__ W2, const float* __restrict__ W3,
    const float* __restrict__ W4, const float* __restrict__ Wp)
{
    __shared__ float stage[256][9];
    const int L  = blockIdx.y;
    const int n0 = blockIdx.x * 8;
    const int t  = threadIdx.x;

    {
        const int k = t;
        if (L < 5) {
            const float* W = (L == 0) ? W0 : (L == 1) ? W1 : (L == 2) ? W2
                           : (L == 3) ? W3 : W4;
            float4 v0 = *(const float4*)&W[k * 256 + n0];
            float4 v1 = *(const float4*)&W[k * 256 + n0 + 4];
            stage[k][0] = v0.x; stage[k][1] = v0.y; stage[k][2] = v0.z; stage[k][3] = v0.w;
            stage[k][4] = v1.x; stage[k][5] = v1.y; stage[k][6] = v1.z; stage[k][7] = v1.w;
        } else {
#pragma unroll
            for (int j = 0; j < 8; j++) {
                int n = n0 + j;
                stage[k][j] = Wp[(n >> 1) * 512 + k * 2 + (n & 1)];
            }
        }
    }
    __syncthreads();
    {
        const int nl = t >> 5;
        const int k0 = (t & 31) * 8;
        __half h[8], l[8];
#pragma unroll
        for (int i = 0; i < 8; i++)
            split2(stage[k0 + i][nl], h[i], l[i]);
        const int n = n0 + nl;
        __half* base = g_Wsplit + (size_t)L * W_LAYER;
        uint4 v;
        v.x = pack2(h[0], h[1]); v.y = pack2(h[2], h[3]);
        v.z = pack2(h[4], h[5]); v.w = pack2(h[6], h[7]);
        *(uint4*)(base + (0 * 256 + n) * 256 + k0) = v;
        v.x = pack2(l[0], l[1]); v.y = pack2(l[2], l[3]);
        v.z = pack2(l[4], l[5]); v.w = pack2(l[6], l[7]);
        *(uint4*)(base + (1 * 256 + n) * 256 + k0) = v;
    }
}

// ---------------------------------------------------------------------------
// prep latents: fp32 [1024][256] -> 2 fp16 split planes
// ---------------------------------------------------------------------------
__global__ __launch_bounds__(256) void prep_latents(
    const float* __restrict__ L, __half* __restrict__ out)
{
    int idx = (blockIdx.x * 256 + threadIdx.x) * 4;
    float4 v = *(const float4*)(L + idx);
    __half h[4], l[4];
    split2(v.x, h[0], l[0]);
    split2(v.y, h[1], l[1]);
    split2(v.z, h[2], l[2]);
    split2(v.w, h[3], l[3]);
    uint2 u;
    u.x = pack2(h[0], h[1]); u.y = pack2(h[2], h[3]);
    *(uint2*)(out + idx) = u;
    u.x = pack2(l[0], l[1]); u.y = pack2(l[2], l[3]);
    *(uint2*)(out + ACT_PLANE + idx) = u;
}

// ---------------------------------------------------------------------------
// layer: Y[1024,256] = (isMu? : relu)(X @ W + bias (+0.5 if mu))
// Tile 32x32, 128 thr (2x2 warps of 16x16), full K=256 staged via cp.async.
// Grid (8 n-tiles, 32 m-tiles) = 256 CTAs, 3 CTAs/SM capacity.
// 3 HMMA products: D0 = hh, D1 = hl + lh; y = D0 + 2^-11*D1.
// ---------------------------------------------------------------------------
__global__ __launch_bounds__(128) void layer_kernel(
    const __half* __restrict__ Ain, const __half* __restrict__ Wsp,
    const float* __restrict__ bias, __half* __restrict__ Aout,
    float* __restrict__ muOut, int isMu)
{
    extern __shared__ char smem[];
    const uint32_t sbase = cvta_smem(smem);
    float* sBias = (float*)(smem + SM_BIAS);

    const int t    = threadIdx.x;
    const int lane = t & 31;
    const int wid  = t >> 5;
    const int n0   = blockIdx.x * 32;
    const int m0   = blockIdx.y * 32;
    const int wm   = (wid & 1) * 16;
    const int wn   = (wid >> 1) * 16;

    // ---- prologue: cp.async A (2x32x256) and B (2x32x256), swizzled ----
#pragma unroll
    for (int i = 0; i < 16; i++) {           // A: 2048 chunks
        int id = i * 128 + t;
        int s = id >> 10;
        int r = (id >> 5) & 31;
        int c = id & 31;
        const void* g = Ain + (size_t)s * ACT_PLANE + ((m0 + r) << 8) + (c << 3);
        cp16(sbase + s * SM_PLANE + (r << 9) + (swz(c, r & 7) << 4), g);
    }
#pragma unroll
    for (int i = 0; i < 16; i++) {           // B: 2048 chunks
        int id = i * 128 + t;
        int s = id >> 10;
        int r = (id >> 5) & 31;
        int c = id & 31;
        const void* g = Wsp + (((s << 8) + n0 + r) << 8) + (c << 3);
        cp16(sbase + SM_B_OFF + s * SM_PLANE + (r << 9) + (swz(c, r & 7) << 4), g);
    }
    if (t < 32) sBias[t] = bias[n0 + t];
    cp_wait_all();
    __syncthreads();

    // ldmatrix per-lane bases
    const uint32_t rowA  = wm + (lane & 15);
    const uint32_t aRowB = sbase + rowA * 512;
    const uint32_t axr   = rowA & 7;
    const uint32_t ahi   = lane >> 4;
    const uint32_t rowB  = wn + ((lane >> 4) << 3) + (lane & 7);
    const uint32_t bRowB = sbase + SM_B_OFF + rowB * 512;
    const uint32_t bxr   = rowB & 7;
    const uint32_t bhi   = (lane >> 3) & 1;

    float D0[2][4] = {}, D1[2][4] = {};

#pragma unroll
    for (int ks = 0; ks < 16; ks++) {
        uint32_t A[2][4], B[2][4];
        uint32_t ca = swz(ks * 2 + ahi, axr) << 4;
        uint32_t cb = swz(ks * 2 + bhi, bxr) << 4;
#pragma unroll
        for (int s = 0; s < 2; s++) {
            ldsm4(A[s], aRowB + s * SM_PLANE + ca);
            ldsm4(B[s], bRowB + s * SM_PLANE + cb);
        }
#pragma unroll
        for (int ni = 0; ni < 2; ni++) {
            const uint32_t* bh = &B[0][ni * 2];
            const uint32_t* bl = &B[1][ni * 2];
            mma16816(D0[ni], A[0], bh);
            mma16816(D1[ni], A[0], bl);
            mma16816(D1[ni], A[1], bh);
        }
    }

    // ---- epilogue ----
    const int crow  = lane >> 2;
    const int ccol2 = (lane & 3) * 2;
#pragma unroll
    for (int ni = 0; ni < 2; ni++) {
        int nl = wn + ni * 8 + ccol2;
        int n  = n0 + nl;
        float b0v = sBias[nl], b1v = sBias[nl + 1];
#pragma unroll
        for (int hh = 0; hh < 2; hh++) {
            float d0 = fmaf(D1[ni][hh * 2],     SC_L, D0[ni][hh * 2]);
            float d1 = fmaf(D1[ni][hh * 2 + 1], SC_L, D0[ni][hh * 2 + 1]);
            int m = m0 + wm + crow + hh * 8;
            if (!isMu) {
                float y0 = fmaxf(d0 + b0v, 0.0f);
                float y1 = fmaxf(d1 + b1v, 0.0f);
                __half h0, l0, h1, l1;
                split2(y0, h0, l0);
                split2(y1, h1, l1);
                *(uint32_t*)(Aout + m * 256 + n)             = pack2(h0, h1);
                *(uint32_t*)(Aout + ACT_PLANE + m * 256 + n) = pack2(l0, l1);
            } else {
                float2 v;
                v.x = d0 + b0v + 0.5f;
                v.y = d1 + b1v + 0.5f;
                *(float2*)(muOut + m * 256 + n) = v;
            }
        }
    }
}

// ---------------------------------------------------------------------------
// Fused tail: one CTA per batch row b; thread = (n, s), tid = 2n + s.
// ---------------------------------------------------------------------------
__global__ __launch_bounds__(256) void tail_kernel(
    const float* __restrict__ realPoints,
    const float* __restrict__ predMu,
    const float* __restrict__ predScale,
    const float* __restrict__ eps,
    float* __restrict__ out)
{
    const int b = blockIdx.x;
    __shared__ float mu_s[256];
    __shared__ float am[128];
    __shared__ float cm[128];
    __shared__ float sc[7];

    const int tid = threadIdx.x;
    mu_s[tid] = g_mu[b * 256 + tid];
    if (tid < 128) {
        float dev = 0.001f + (float)tid * (0.009f / 127.0f);
        am[tid] = -0.5f / (dev * dev);
        cm[tid] = -2.0f * logf(dev) - LOG2PI_F;
    }
    if (tid == 0) {
        sc[0] = realPoints[b * 2];
        sc[1] = realPoints[b * 2 + 1];
        sc[2] = predMu[b * 2];
        sc[3] = predMu[b * 2 + 1];
        float p0 = predScale[b * 2], p1 = predScale[b * 2 + 1];
        sc[4] = 1.0f / p0;
        sc[5] = 1.0f / p1;
        sc[6] = logf(p0) + logf(p1);
    }
    __syncthreads();

    const int n = tid >> 1;
    const int s = tid & 1;

    const float mu0 = mu_s[2 * n];
    const float mu1 = mu_s[2 * n + 1];
    const float dev = 0.001f + (float)n * (0.009f / 127.0f);

    const int eoff = s * (BSZ * NPTS * 2) + (b * NPTS + n) * 2;
    const float e0 = eps[eoff];
    const float e1 = eps[eoff + 1];
    const float s0 = fmaf(dev, e0, mu0);
    const float s1 = fmaf(dev, e1, mu1);

    {
        long so = ((long)(s * NPTS + n) * BSZ + b) * 2;
        out[OFF_SAMPLED + so]     = s0;
        out[OFF_SAMPLED + so + 1] = s1;
    }

    float sumexp = 0.0f;
    float en = 0.0f;
#pragma unroll 4
    for (int m = 0; m < 128; m++) {
        float d0 = s0 - mu_s[2 * m];
        float d1 = s1 - mu_s[2 * m + 1];
        float ss = fmaf(d0, d0, d1 * d1);
        float lb = fmaf(ss, am[m], cm[m]);
        float e  = __expf(lb);
        sumexp += e;
        if (m == n) en = e;
    }
    float diag = en / sumexp;
    float lbv  = 1.0f - diag;
    out[OFF_LOSSB + b * 256 + tid] = lbv * lbv;

    float z0 = (s0 - sc[2]) * sc[4];
    float z1 = (s1 - sc[3]) * sc[5];
    float lp = fmaf(-0.5f, fmaf(z0, z0, z1 * z1), -sc[6] - LOG2PI_F);
    float gl  = 1.0f / (1.0f + __expf(-lp));
    float sgn = 1.0f / (1.0f + __expf(lp));
    float tA  = LOG1P_HALF - log1pf(sgn);
    tA *= tA;

    float gl_o = __shfl_xor_sync(0xffffffffu, gl, 1);
    float tA_o = __shfl_xor_sync(0xffffffffu, tA, 1);

    if (s == 0) {
        float glm   = 0.5f * (gl + gl_o);
        float lossA = 0.5f * (tA + tA_o);
        float dr0 = sc[0] - mu0;
        float dr1 = sc[1] - mu1;
        float ssr = fmaf(dr0, dr0, dr1 * dr1);
        float rlp = fmaf(ssr, am[n], cm[n]);
        float rl  = 1.0f / (1.0f + __expf(-rlp));
        out[OFF_REAL  + b * NPTS + n] = rl;
        out[OFF_LOSSA + b * NPTS + n] = lossA;
        out[OFF_GEN   + b * NPTS + n] = glm * (1.0f - rl);
    }
}

// ---------------------------------------------------------------------------
extern "C" void kernel_launch(void* const* d_in, const int* in_sizes, int n_in,
                              void* d_out, int out_size) {
    const float* latents    = (const float*)d_in[0];
    const float* realPoints = (const float*)d_in[1];
    const float* predMu     = (const float*)d_in[2];
    const float* predScale  = (const float*)d_in[3];
    const float* eps        = (const float*)d_in[4];
    const float* W[5]  = {(const float*)d_in[5],  (const float*)d_in[7],
                          (const float*)d_in[9],  (const float*)d_in[11],
                          (const float*)d_in[13]};
    const float* bb[5] = {(const float*)d_in[6],  (const float*)d_in[8],
                          (const float*)d_in[10], (const float*)d_in[12],
                          (const float*)d_in[14]};
    const float* bp = (const float*)d_in[16];
    float* out = (float*)d_out;

    __half *gA, *gW;
    float* mu;
    cudaGetSymbolAddress((void**)&gA, g_Act);
    cudaGetSymbolAddress((void**)&gW, g_Wsplit);
    cudaGetSymbolAddress((void**)&mu, g_mu);
    __half* A0 = gA;
    __half* A1 = gA + 2 * (size_t)ACT_PLANE;

    cudaFuncSetAttribute(layer_kernel,
                         cudaFuncAttributeMaxDynamicSharedMemorySize, SM_TOTAL);

    prep_weights<<<dim3(32, 6), 256>>>(W[0], W[1], W[2], W[3], W[4],
                                       (const float*)d_in[15]);
    prep_latents<<<256, 256>>>(latents, A0);

    dim3 grid(8, 32);
    layer_kernel<<<grid, 128, SM_TOTAL>>>(A0, gW + 0 * (size_t)W_LAYER, bb[0], A1, mu, 0);
    layer_kernel<<<grid, 128, SM_TOTAL>>>(A1, gW + 1 * (size_t)W_LAYER, bb[1], A0, mu, 0);
    layer_kernel<<<grid, 128, SM_TOTAL>>>(A0, gW + 2 * (size_t)W_LAYER, bb[2], A1, mu, 0);
    layer_kernel<<<grid, 128, SM_TOTAL>>>(A1, gW + 3 * (size_t)W_LAYER, bb[3], A0, mu, 0);
    layer_kernel<<<grid, 128, SM_TOTAL>>>(A0, gW + 4 * (size_t)W_LAYER, bb[4], A1, mu, 0);
    layer_kernel<<<grid, 128, SM_TOTAL>>>(A1, gW + 5 * (size_t)W_LAYER, bp, A0, mu, 1);

    tail_kernel<<<BSZ, 256>>>(realPoints, predMu, predScale, eps, out);
}

// round 9
// speedup vs baseline: 1.9808x; 1.0006x over previous
#include <cuda_runtime.h>
#include <cuda.h>
#include <cuda_fp16.h>
#include <math.h>
#include <stdint.h>

// Problem constants
#define BSZ   1024
#define NPTS  128
#define LOG2PI_F 1.8378770664093453f
#define LOG1P_HALF 0.40546510810816438f

// Output layout offsets
#define OFF_SAMPLED 0
#define OFF_GEN     524288
#define OFF_REAL    655360
#define OFF_LOSSA   786432
#define OFF_LOSSB   917504

// 2-way split: a = h + l'*2^-11  (residual ~2^-22)
#define SC_L 4.8828125e-4f            // 2^-11

#define ACT_PLANE 262144              // halves per activation plane (1024*256)
#define W_LAYER   (2 * 256 * 256)     // halves per layer of split weights

// Layer smem: A 4 kchunks x [2 planes][32 rows][128B] = 32KB, B same, + mbar
#define SM_A     0
#define SM_B     32768
#define SM_MBAR  65536
#define SM_TOTAL 65664

// Scratch (128B aligned for TMA)
__device__ __align__(128) __half g_Act[2][2 * ACT_PLANE];  // ping-pong split acts
__device__ __align__(128) __half g_Wsplit[6 * W_LAYER];    // [L][split][n][k]
__device__ float g_mu[BSZ * 256];

// ---------------------------------------------------------------------------
// helpers
// ---------------------------------------------------------------------------
__device__ __forceinline__ uint32_t cvta_smem(const void* p) {
    uint32_t a;
    asm("{ .reg .u64 t; cvta.to.shared.u64 t, %1; cvt.u32.u64 %0, t; }"
        : "=r"(a) : "l"(p));
    return a;
}
__device__ __forceinline__ void ldsm4(uint32_t* r, uint32_t addr) {
    asm volatile("ldmatrix.sync.aligned.m8n8.x4.shared.b16 {%0,%1,%2,%3}, [%4];"
                 : "=r"(r[0]), "=r"(r[1]), "=r"(r[2]), "=r"(r[3]) : "r"(addr));
}
__device__ __forceinline__ void mma16816(float* d, const uint32_t* a, const uint32_t* b) {
    asm("mma.sync.aligned.m16n8k16.row.col.f32.f16.f16.f32 "
        "{%0,%1,%2,%3}, {%4,%5,%6,%7}, {%8,%9}, {%0,%1,%2,%3};"
        : "+f"(d[0]), "+f"(d[1]), "+f"(d[2]), "+f"(d[3])
        : "r"(a[0]), "r"(a[1]), "r"(a[2]), "r"(a[3]), "r"(b[0]), "r"(b[1]));
}
__device__ __forceinline__ void mbar_init(uint32_t a, uint32_t cnt) {
    asm volatile("mbarrier.init.shared.b64 [%0], %1;" :: "r"(a), "r"(cnt) : "memory");
}
__device__ __forceinline__ void mbar_expect_tx(uint32_t a, uint32_t bytes) {
    asm volatile("mbarrier.arrive.expect_tx.shared.b64 _, [%0], %1;"
                 :: "r"(a), "r"(bytes) : "memory");
}
__device__ __forceinline__ void mbar_wait_p0(uint32_t mbar) {
    asm volatile(
        "{\n\t.reg .pred P1;\n\t"
        "WAIT_LOOP_%=:\n\t"
        "mbarrier.try_wait.parity.shared::cta.b64 P1, [%0], 0, 0x989680;\n\t"
        "@P1 bra.uni WAIT_DONE_%=;\n\t"
        "bra.uni WAIT_LOOP_%=;\n\t"
        "WAIT_DONE_%=:\n\t}"
        :: "r"(mbar) : "memory");
}
__device__ __forceinline__ void tma3d(uint32_t sdst, const CUtensorMap* tm,
                                      int x, int y, int z, uint32_t mbar) {
    asm volatile(
        "cp.async.bulk.tensor.3d.shared::cta.global.tile.mbarrier::complete_tx::bytes "
        "[%0], [%1, {%2, %3, %4}], [%5];"
        :: "r"(sdst), "l"(tm), "r"(x), "r"(y), "r"(z), "r"(mbar) : "memory");
}
// 2-way fp16 split, low term rescaled to fp16-normal range
__device__ __forceinline__ void split2(float a, __half& h, __half& l) {
    h = __float2half_rn(a);
    float r1 = a - __half2float(h);
    l = __float2half_rn(r1 * 2048.0f);
}
__device__ __forceinline__ uint32_t pack2(__half a, __half b) {
    __half2 h = __halves2half2(a, b);
    return *(uint32_t*)&h;
}

// ---------------------------------------------------------------------------
// prep: g_Wsplit[L][s][n][k] fp16 2-split of W_L^T (L=5 is Wp reshaped)
// ---------------------------------------------------------------------------
__global__ __launch_bounds__(256) void prep_weights(
    const float* __restrict__ W0, const float* __restrict__ W1,
    const float* __restrict__ W2, const float* __restrict__ W3,
    const float* __restrict__ W4, const float* __restrict__ Wp)
{
    __shared__ float stage[256][9];
    const int L  = blockIdx.y;
    const int n0 = blockIdx.x * 8;
    const int t  = threadIdx.x;

    {
        const int k = t;
        if (L < 5) {
            const float* W = (L == 0) ? W0 : (L == 1) ? W1 : (L == 2) ? W2
                           : (L == 3) ? W3 : W4;
            float4 v0 = *(const float4*)&W[k * 256 + n0];
            float4 v1 = *(const float4*)&W[k * 256 + n0 + 4];
            stage[k][0] = v0.x; stage[k][1] = v0.y; stage[k][2] = v0.z; stage[k][3] = v0.w;
            stage[k][4] = v1.x; stage[k][5] = v1.y; stage[k][6] = v1.z; stage[k][7] = v1.w;
        } else {
#pragma unroll
            for (int j = 0; j < 8; j++) {
                int n = n0 + j;
                stage[k][j] = Wp[(n >> 1) * 512 + k * 2 + (n & 1)];
            }
        }
    }
    __syncthreads();
    {
        const int nl = t >> 5;
        const int k0 = (t & 31) * 8;
        __half h[8], l[8];
#pragma unroll
        for (int i = 0; i < 8; i++)
            split2(stage[k0 + i][nl], h[i], l[i]);
        const int n = n0 + nl;
        __half* base = g_Wsplit + (size_t)L * W_LAYER;
        uint4 v;
        v.x = pack2(h[0], h[1]); v.y = pack2(h[2], h[3]);
        v.z = pack2(h[4], h[5]); v.w = pack2(h[6], h[7]);
        *(uint4*)(base + (0 * 256 + n) * 256 + k0) = v;
        v.x = pack2(l[0], l[1]); v.y = pack2(l[2], l[3]);
        v.z = pack2(l[4], l[5]); v.w = pack2(l[6], l[7]);
        *(uint4*)(base + (1 * 256 + n) * 256 + k0) = v;
    }
}

// ---------------------------------------------------------------------------
// prep latents: fp32 [1024][256] -> 2 fp16 split planes
// ---------------------------------------------------------------------------
__global__ __launch_bounds__(256) void prep_latents(
    const float* __restrict__ L, __half* __restrict__ out)
{
    int idx = (blockIdx.x * 256 + threadIdx.x) * 4;
    float4 v = *(const float4*)(L + idx);
    __half h[4], l[4];
    split2(v.x, h[0], l[0]);
    split2(v.y, h[1], l[1]);
    split2(v.z, h[2], l[2]);
    split2(v.w, h[3], l[3]);
    uint2 u;
    u.x = pack2(h[0], h[1]); u.y = pack2(h[2], h[3]);
    *(uint2*)(out + idx) = u;
    u.x = pack2(l[0], l[1]); u.y = pack2(l[2], l[3]);
    *(uint2*)(out + ACT_PLANE + idx) = u;
}

// ---------------------------------------------------------------------------
// layer: Y[1024,256] = (isMu? : relu)(X @ W + bias (+0.5 if mu))
// Tile 32x32, 128 thr (2x2 warps of 16x16), K=256 staged via 8 TMA loads.
// smem blocks: [kchunk(4)][plane(2)][row(32)][128B], SW128 swizzle.
// 3 HMMA products: D0 = hh, D1 = hl + lh; y = D0 + 2^-11*D1.
// ---------------------------------------------------------------------------
__global__ __launch_bounds__(128) void layer_kernel(
    const __grid_constant__ CUtensorMap tmA,
    const __grid_constant__ CUtensorMap tmW,
    int bufZ, int layerZ,
    const float* __restrict__ bias,
    __half* __restrict__ Aout, float* __restrict__ muOut, int isMu)
{
    extern __shared__ char smem[];
    const uint32_t sbase = cvta_smem(smem);
    const uint32_t mbar  = sbase + SM_MBAR;

    const int t    = threadIdx.x;
    const int lane = t & 31;
    const int wid  = t >> 5;
    const int n0   = blockIdx.x * 32;
    const int m0   = blockIdx.y * 32;
    const int wm   = (wid & 1) * 16;
    const int wn   = (wid >> 1) * 16;

    if (t == 0) mbar_init(mbar, 1);
    __syncthreads();
    if (t == 0) {
        mbar_expect_tx(mbar, 65536);
#pragma unroll
        for (int q = 0; q < 4; q++) {
            tma3d(sbase + SM_A + q * 8192, &tmA, q * 64, m0, bufZ,   mbar);
            tma3d(sbase + SM_B + q * 8192, &tmW, q * 64, n0, layerZ, mbar);
        }
    }
    mbar_wait_p0(mbar);

    // ldmatrix per-lane bases: addr = block + q*8192 + s*4096 + r*128 + swz(c,r)*16
    const uint32_t rowA = wm + (lane & 15);
    const uint32_t ahi  = lane >> 4;
    const uint32_t aRow = sbase + SM_A + rowA * 128;
    const uint32_t axr  = rowA & 7;
    const uint32_t rowB = wn + ((lane >> 4) << 3) + (lane & 7);
    const uint32_t bhi  = (lane >> 3) & 1;
    const uint32_t bRow = sbase + SM_B + rowB * 128;
    const uint32_t bxr  = rowB & 7;

    float D0[2][4] = {}, D1[2][4] = {};

#pragma unroll
    for (int ks = 0; ks < 16; ks++) {
        const uint32_t q  = ks >> 2;
        const uint32_t ca = ((((ks & 3) << 1) | ahi) ^ axr) << 4;
        const uint32_t cb = ((((ks & 3) << 1) | bhi) ^ bxr) << 4;
        uint32_t A[2][4], B[2][4];
#pragma unroll
        for (int s = 0; s < 2; s++) {
            ldsm4(A[s], aRow + q * 8192 + s * 4096 + ca);
            ldsm4(B[s], bRow + q * 8192 + s * 4096 + cb);
        }
#pragma unroll
        for (int ni = 0; ni < 2; ni++) {
            const uint32_t* bh = &B[0][ni * 2];
            const uint32_t* bl = &B[1][ni * 2];
            mma16816(D0[ni], A[0], bh);
            mma16816(D1[ni], A[0], bl);
            mma16816(D1[ni], A[1], bh);
        }
    }

    // ---- epilogue ----
    const int crow  = lane >> 2;
    const int ccol2 = (lane & 3) * 2;
#pragma unroll
    for (int ni = 0; ni < 2; ni++) {
        int n = n0 + wn + ni * 8 + ccol2;
        float b0v = __ldg(&bias[n]);
        float b1v = __ldg(&bias[n + 1]);
#pragma unroll
        for (int hh = 0; hh < 2; hh++) {
            float d0 = fmaf(D1[ni][hh * 2],     SC_L, D0[ni][hh * 2]);
            float d1 = fmaf(D1[ni][hh * 2 + 1], SC_L, D0[ni][hh * 2 + 1]);
            int m = m0 + wm + crow + hh * 8;
            if (!isMu) {
                float y0 = fmaxf(d0 + b0v, 0.0f);
                float y1 = fmaxf(d1 + b1v, 0.0f);
                __half h0, l0, h1, l1;
                split2(y0, h0, l0);
                split2(y1, h1, l1);
                *(uint32_t*)(Aout + m * 256 + n)             = pack2(h0, h1);
                *(uint32_t*)(Aout + ACT_PLANE + m * 256 + n) = pack2(l0, l1);
            } else {
                float2 v;
                v.x = d0 + b0v + 0.5f;
                v.y = d1 + b1v + 0.5f;
                *(float2*)(muOut + m * 256 + n) = v;
            }
        }
    }
}

// ---------------------------------------------------------------------------
// Fused tail: one CTA per batch row b; thread = (n, s), tid = 2n + s.
// ---------------------------------------------------------------------------
__global__ __launch_bounds__(256) void tail_kernel(
    const float* __restrict__ realPoints,
    const float* __restrict__ predMu,
    const float* __restrict__ predScale,
    const float* __restrict__ eps,
    float* __restrict__ out)
{
    const int b = blockIdx.x;
    __shared__ float mu_s[256];
    __shared__ float am[128];
    __shared__ float cm[128];
    __shared__ float sc[7];

    const int tid = threadIdx.x;
    mu_s[tid] = g_mu[b * 256 + tid];
    if (tid < 128) {
        float dev = 0.001f + (float)tid * (0.009f / 127.0f);
        am[tid] = -0.5f / (dev * dev);
        cm[tid] = -2.0f * logf(dev) - LOG2PI_F;
    }
    if (tid == 0) {
        sc[0] = realPoints[b * 2];
        sc[1] = realPoints[b * 2 + 1];
        sc[2] = predMu[b * 2];
        sc[3] = predMu[b * 2 + 1];
        float p0 = predScale[b * 2], p1 = predScale[b * 2 + 1];
        sc[4] = 1.0f / p0;
        sc[5] = 1.0f / p1;
        sc[6] = logf(p0) + logf(p1);
    }
    __syncthreads();

    const int n = tid >> 1;
    const int s = tid & 1;

    const float mu0 = mu_s[2 * n];
    const float mu1 = mu_s[2 * n + 1];
    const float dev = 0.001f + (float)n * (0.009f / 127.0f);

    const int eoff = s * (BSZ * NPTS * 2) + (b * NPTS + n) * 2;
    const float e0 = eps[eoff];
    const float e1 = eps[eoff + 1];
    const float s0 = fmaf(dev, e0, mu0);
    const float s1 = fmaf(dev, e1, mu1);

    {
        long so = ((long)(s * NPTS + n) * BSZ + b) * 2;
        out[OFF_SAMPLED + so]     = s0;
        out[OFF_SAMPLED + so + 1] = s1;
    }

    float sumexp = 0.0f;
    float en = 0.0f;
#pragma unroll 4
    for (int m = 0; m < 128; m++) {
        float d0 = s0 - mu_s[2 * m];
        float d1 = s1 - mu_s[2 * m + 1];
        float ss = fmaf(d0, d0, d1 * d1);
        float lb = fmaf(ss, am[m], cm[m]);
        float e  = __expf(lb);
        sumexp += e;
        if (m == n) en = e;
    }
    float diag = en / sumexp;
    float lbv  = 1.0f - diag;
    out[OFF_LOSSB + b * 256 + tid] = lbv * lbv;

    float z0 = (s0 - sc[2]) * sc[4];
    float z1 = (s1 - sc[3]) * sc[5];
    float lp = fmaf(-0.5f, fmaf(z0, z0, z1 * z1), -sc[6] - LOG2PI_F);
    float gl  = 1.0f / (1.0f + __expf(-lp));
    float sgn = 1.0f / (1.0f + __expf(lp));
    float tA  = LOG1P_HALF - log1pf(sgn);
    tA *= tA;

    float gl_o = __shfl_xor_sync(0xffffffffu, gl, 1);
    float tA_o = __shfl_xor_sync(0xffffffffu, tA, 1);

    if (s == 0) {
        float glm   = 0.5f * (gl + gl_o);
        float lossA = 0.5f * (tA + tA_o);
        float dr0 = sc[0] - mu0;
        float dr1 = sc[1] - mu1;
        float ssr = fmaf(dr0, dr0, dr1 * dr1);
        float rlp = fmaf(ssr, am[n], cm[n]);
        float rl  = 1.0f / (1.0f + __expf(-rlp));
        out[OFF_REAL  + b * NPTS + n] = rl;
        out[OFF_LOSSA + b * NPTS + n] = lossA;
        out[OFF_GEN   + b * NPTS + n] = glm * (1.0f - rl);
    }
}

// ---------------------------------------------------------------------------
typedef CUresult (*encode_fn_t)(
    CUtensorMap*, CUtensorMapDataType, cuuint32_t, void*,
    const cuuint64_t*, const cuuint64_t*, const cuuint32_t*, const cuuint32_t*,
    CUtensorMapInterleave, CUtensorMapSwizzle, CUtensorMapL2promotion,
    CUtensorMapFloatOOBfill);

static void encode3d(encode_fn_t fn, CUtensorMap* tm, void* base,
                     unsigned long long d2, unsigned long long s2bytes) {
    cuuint64_t dims[3]    = {256, 0, d2};
    dims[1] = (d2 == 12) ? 256 : 1024;
    cuuint64_t strides[2] = {512, s2bytes};
    cuuint32_t box[3]     = {64, 32, 2};
    cuuint32_t es[3]      = {1, 1, 1};
    fn(tm, CU_TENSOR_MAP_DATA_TYPE_FLOAT16, 3, base, dims, strides, box, es,
       CU_TENSOR_MAP_INTERLEAVE_NONE, CU_TENSOR_MAP_SWIZZLE_128B,
       CU_TENSOR_MAP_L2_PROMOTION_L2_128B, CU_TENSOR_MAP_FLOAT_OOB_FILL_NONE);
}

extern "C" void kernel_launch(void* const* d_in, const int* in_sizes, int n_in,
                              void* d_out, int out_size) {
    const float* latents    = (const float*)d_in[0];
    const float* realPoints = (const float*)d_in[1];
    const float* predMu     = (const float*)d_in[2];
    const float* predScale  = (const float*)d_in[3];
    const float* eps        = (const float*)d_in[4];
    const float* W[5]  = {(const float*)d_in[5],  (const float*)d_in[7],
                          (const float*)d_in[9],  (const float*)d_in[11],
                          (const float*)d_in[13]};
    const float* bb[5] = {(const float*)d_in[6],  (const float*)d_in[8],
                          (const float*)d_in[10], (const float*)d_in[12],
                          (const float*)d_in[14]};
    const float* bp = (const float*)d_in[16];
    float* out = (float*)d_out;

    __half *gA, *gW;
    float* mu;
    cudaGetSymbolAddress((void**)&gA, g_Act);
    cudaGetSymbolAddress((void**)&gW, g_Wsplit);
    cudaGetSymbolAddress((void**)&mu, g_mu);
    __half* A0 = gA;
    __half* A1 = gA + 2 * (size_t)ACT_PLANE;

    // tensormaps (driver entry point via runtime API; no -lcuda needed)
    void* fptr = nullptr;
    cudaDriverEntryPointQueryResult qr;
    cudaGetDriverEntryPoint("cuTensorMapEncodeTiled", &fptr,
                            cudaEnableDefault, &qr);
    encode_fn_t enc = (encode_fn_t)fptr;
    CUtensorMap tmA, tmW;
    encode3d(enc, &tmA, gA, 4,  (unsigned long long)ACT_PLANE * 2);  // acts: 4 planes
    encode3d(enc, &tmW, gW, 12, 131072ull);                          // weights: 12 planes

    cudaFuncSetAttribute(layer_kernel,
                         cudaFuncAttributeMaxDynamicSharedMemorySize, SM_TOTAL);

    prep_weights<<<dim3(32, 6), 256>>>(W[0], W[1], W[2], W[3], W[4],
                                       (const float*)d_in[15]);
    prep_latents<<<256, 256>>>(latents, A0);

    dim3 grid(8, 32);
    layer_kernel<<<grid, 128, SM_TOTAL>>>(tmA, tmW, 0, 0,  bb[0], A1, mu, 0);
    layer_kernel<<<grid, 128, SM_TOTAL>>>(tmA, tmW, 2, 2,  bb[1], A0, mu, 0);
    layer_kernel<<<grid, 128, SM_TOTAL>>>(tmA, tmW, 0, 4,  bb[2], A1, mu, 0);
    layer_kernel<<<grid, 128, SM_TOTAL>>>(tmA, tmW, 2, 6,  bb[3], A0, mu, 0);
    layer_kernel<<<grid, 128, SM_TOTAL>>>(tmA, tmW, 0, 8,  bb[4], A1, mu, 0);
    layer_kernel<<<grid, 128, SM_TOTAL>>>(tmA, tmW, 2, 10, bp,    A0, mu, 1);

    tail_kernel<<<BSZ, 256>>>(realPoints, predMu, predScale, eps, out);
}